// round 16
// baseline (speedup 1.0000x reference)
#include <cuda_runtime.h>
#include <math_constants.h>

// Problem shapes (PointCloudMeshGridLoss_79070347920145)
#define NB 2
#define NP 8192
#define NV 4098
#define NF 8192
#define EPSF 1e-12f

#define THREADS     256
#define PTS_BLOCK   512               // 2 points per thread (packed f32x2)
#define PTILES      16                // NP / PTS_BLOCK
#define SLICES      8
#define TRI_SLICE   1024              // NF / SLICES
#define MAIN_BLOCKS (NB * PTILES * SLICES)   // 256
#define CORR_BLOCKS 64                // NB * (NP/256)
#define DEG_MAX     512

typedef unsigned long long u64;

// Screen consts per tri: (nx,ny),(nz,c3z) pre-duplicated = 2 ulonglong2 (32B)
__device__ ulonglong2 g_scr[NB * NF * 2];
// Full consts per tri: 18 u64 = 9 ulonglong2 (144B)
// j0:(nax,nay) j1:(naz,abx) j2:(aby,abz) j3:(acx,acy) j4:(acz,aa)
// j5:(cc,nad)  j6:(amd,bb)  j7:(raa,rcc) j8:(rbb,den)
__device__ ulonglong2 g_tri[NB * NF * 9];
__device__ float      g_mind2[NB * NP];
__device__ int        g_degcnt[NB];
__device__ int        g_deglist[NB][DEG_MAX];

// ---------------- packed f32x2 helpers ----------------
__device__ __forceinline__ u64 pk2(float lo, float hi) {
    return ((u64)__float_as_uint(hi) << 32) | (u64)__float_as_uint(lo);
}
__device__ __forceinline__ float lo2(u64 v) { return __uint_as_float((unsigned)v); }
__device__ __forceinline__ float hi2(u64 v) { return __uint_as_float((unsigned)(v >> 32)); }
__device__ __forceinline__ u64 f2fma(u64 a, u64 b, u64 c) {
    u64 d; asm("fma.rn.f32x2 %0, %1, %2, %3;" : "=l"(d) : "l"(a), "l"(b), "l"(c)); return d;
}
__device__ __forceinline__ u64 f2mul(u64 a, u64 b) {
    u64 d; asm("mul.rn.f32x2 %0, %1, %2;" : "=l"(d) : "l"(a), "l"(b)); return d;
}
__device__ __forceinline__ u64 f2add(u64 a, u64 b) {
    u64 d; asm("add.rn.f32x2 %0, %1, %2;" : "=l"(d) : "l"(a), "l"(b)); return d;
}
__device__ __forceinline__ u64 f2clamp(u64 v, u64 hi) {   // per-half clamp to [0, hi]
    float a = fminf(fmaxf(lo2(v), 0.0f), lo2(hi));
    float b = fminf(fmaxf(hi2(v), 0.0f), hi2(hi));
    return pk2(a, b);
}

// ---------------------------------------------------------------------------
// Kernel 1: init
// ---------------------------------------------------------------------------
__global__ void init_kernel() {
    int i = blockIdx.x * blockDim.x + threadIdx.x;
    if (i < NB * NP) g_mind2[i] = CUDART_INF_F;
    if (i < NB) g_degcnt[i] = 0;
}

// ---------------------------------------------------------------------------
// Kernel 2: per-triangle precompute
// ---------------------------------------------------------------------------
__global__ void prep_kernel(const float* __restrict__ verts,
                            const int*   __restrict__ faces) {
    int idx = blockIdx.x * blockDim.x + threadIdx.x;
    if (idx >= NB * NF) return;
    int b = idx / NF;

    const int* fc = faces + (size_t)idx * 3;
    const float* vb = verts + (size_t)b * NV * 3;
    int ia = fc[0], ib = fc[1], ic = fc[2];

    float ax = vb[ia * 3 + 0], ay = vb[ia * 3 + 1], az = vb[ia * 3 + 2];
    float bx = vb[ib * 3 + 0], by = vb[ib * 3 + 1], bz = vb[ib * 3 + 2];
    float cx = vb[ic * 3 + 0], cy = vb[ic * 3 + 1], cz = vb[ic * 3 + 2];

    float abx = bx - ax, aby = by - ay, abz = bz - az;
    float acx = cx - ax, acy = cy - ay, acz = cz - az;

    float aa = abx * abx + aby * aby + abz * abz;
    float ad = abx * acx + aby * acy + abz * acz;
    float cc = acx * acx + acy * acy + acz * acz;
    float bb = aa + cc - 2.0f * ad;                 // |bc|^2
    float den = aa * cc - ad * ad;                  // |ab x ac|^2

    bool deg = (aa < 1e-9f) || (cc < 1e-9f) || (bb < 1e-9f) || (den < 1e-6f);
    if (deg) {
        int w = atomicAdd(&g_degcnt[b], 1);
        if (w < DEG_MAX) g_deglist[b][w] = idx - b * NF;
    }

    float raa = 1.0f / fmaxf(aa, EPSF);
    float rcc = 1.0f / fmaxf(cc, EPSF);
    float rbb = 1.0f / fmaxf(bb, EPSF);

    // unit normal (screen lower bound); disabled for degenerate faces
    float nxv = aby * acz - abz * acy;
    float nyv = abz * acx - abx * acz;
    float nzv = abx * acy - aby * acx;
    float rn = rsqrtf(fmaxf(den, 1e-30f));
    nxv *= rn; nyv *= rn; nzv *= rn;
    float c3z = -(nxv * ax + nyv * ay + nzv * az);
    if (deg) { nxv = 0.0f; nyv = 0.0f; nzv = 0.0f; c3z = 1e30f; }

#define DUP(x) pk2((x), (x))
    ulonglong2* sc = &g_scr[(size_t)idx * 2];
    sc[0] = make_ulonglong2(DUP(nxv), DUP(nyv));
    sc[1] = make_ulonglong2(DUP(nzv), DUP(c3z));

    ulonglong2* o = &g_tri[(size_t)idx * 9];
    o[0] = make_ulonglong2(DUP(-ax), DUP(-ay));
    o[1] = make_ulonglong2(DUP(-az), DUP(abx));
    o[2] = make_ulonglong2(DUP(aby), DUP(abz));
    o[3] = make_ulonglong2(DUP(acx), DUP(acy));
    o[4] = make_ulonglong2(DUP(acz), DUP(aa));
    o[5] = make_ulonglong2(DUP(cc),  DUP(-ad));
    o[6] = make_ulonglong2(DUP(aa - ad), DUP(bb));
    o[7] = make_ulonglong2(DUP(raa), DUP(rcc));
    o[8] = make_ulonglong2(DUP(rbb), DUP(den));
#undef DUP
}

// ---------------------------------------------------------------------------
// Exact reference cascade for one (point, triangle) — used by correction.
// ---------------------------------------------------------------------------
__device__ float cascade_dist2(float ppx, float ppy, float ppz,
                               const float* vb, const int* fc) {
    int ia = fc[0], ibv = fc[1], ic = fc[2];
    float ax = vb[ia * 3 + 0], ay = vb[ia * 3 + 1], az = vb[ia * 3 + 2];
    float bx = vb[ibv * 3 + 0], by = vb[ibv * 3 + 1], bz = vb[ibv * 3 + 2];
    float cx = vb[ic * 3 + 0], cy = vb[ic * 3 + 1], cz = vb[ic * 3 + 2];

    float abx = bx - ax, aby = by - ay, abz = bz - az;
    float acx = cx - ax, acy = cy - ay, acz = cz - az;

    float aa = abx * abx + aby * aby + abz * abz;
    float ad = abx * acx + aby * acy + abz * acz;
    float cc = acx * acx + acy * acy + acz * acz;
    float bbq = aa + cc - 2.0f * ad;
    float den = aa * cc - ad * ad;

    float raa  = 1.0f / fmaxf(aa, EPSF);
    float rcc  = 1.0f / fmaxf(cc, EPSF);
    float rbb  = 1.0f / fmaxf(bbq, EPSF);
    float rden = 1.0f / fmaxf(den, EPSF);

    float apx = ppx - ax, apy = ppy - ay, apz = ppz - az;

    float d1 = fmaf(abx, apx, fmaf(aby, apy, abz * apz));
    float d2 = fmaf(acx, apx, fmaf(acy, apy, acz * apz));
    float d3 = d1 - aa;
    float d4 = d2 - ad;
    float d5 = d1 - ad;
    float d6 = d2 - cc;

    float va = d3 * d6 - d5 * d4;
    float vbv = d5 * d2 - d1 * d6;
    float vcv = d1 * d4 - d3 * d2;

    float s = vbv * rden;
    float w = vcv * rden;

    float e46 = d4 - d3;
    float e56 = d5 - d6;
    bool c6 = (va <= 0.0f) && (e46 >= 0.0f) && (e56 >= 0.0f);
    float wbc = e46 * rbb;
    s = c6 ? (1.0f - wbc) : s;
    w = c6 ? wbc : w;

    bool c5 = (vbv <= 0.0f) && (d2 >= 0.0f) && (d6 <= 0.0f);
    s = c5 ? 0.0f : s;
    w = c5 ? (d2 * rcc) : w;

    bool c4 = (vcv <= 0.0f) && (d1 >= 0.0f) && (d3 <= 0.0f);
    s = c4 ? (d1 * raa) : s;
    w = c4 ? 0.0f : w;

    bool c3 = (d6 >= 0.0f) && (d5 <= d6);
    s = c3 ? 0.0f : s;
    w = c3 ? 1.0f : w;

    bool c2 = (d3 >= 0.0f) && (d4 <= d3);
    s = c2 ? 1.0f : s;
    w = c2 ? 0.0f : w;

    bool c1 = (d1 <= 0.0f) && (d2 <= 0.0f);
    s = c1 ? 0.0f : s;
    w = c1 ? 0.0f : w;

    float rx = apx - fmaf(s, abx, w * acx);
    float ry = apy - fmaf(s, aby, w * acy);
    float rz = apz - fmaf(s, abz, w * acz);
    return fmaf(rx, rx, fmaf(ry, ry, rz * rz));
}

// ---------------------------------------------------------------------------
// Kernel 3: main — plane-distance screening + rare full evaluation.
// Blocks [0,64): correction for degenerate faces (exact reference cascade).
// Blocks [64,320): screened scan.
// ---------------------------------------------------------------------------
__global__ __launch_bounds__(THREADS, 2)
void main_kernel(const float* __restrict__ points,
                 const float* __restrict__ verts,
                 const int*   __restrict__ faces) {
    __shared__ ulonglong2 s_scr[TRI_SLICE * 2];   // 32 KB

    if (blockIdx.x < CORR_BLOCKS) {
        // ---- correction role ----
        int cbid = blockIdx.x;
        int b = cbid >> 5;                         // 32 blocks per batch
        int n = min(g_degcnt[b], DEG_MAX);
        if (n == 0) return;
        int p = (cbid & 31) * THREADS + threadIdx.x;
        const float* pp_ = points + ((size_t)b * NP + p) * 3;
        float ppx = pp_[0], ppy = pp_[1], ppz = pp_[2];
        const float* vb = verts + (size_t)b * NV * 3;
        float best = CUDART_INF_F;
        for (int df = 0; df < n; ++df) {
            int f = g_deglist[b][df];
            best = fminf(best, cascade_dist2(ppx, ppy, ppz, vb,
                                             faces + ((size_t)b * NF + f) * 3));
        }
        best = fmaxf(best, 0.0f);
        atomicMin((int*)&g_mind2[b * NP + p], __float_as_int(best));
        return;
    }

    // ---- main role ----
    int bid   = blockIdx.x - CORR_BLOCKS;          // 0..255
    int b     = bid >> 7;                          // 128 blocks per batch
    int rem   = bid & 127;
    int ptile = rem >> 3;
    int slice = rem & 7;
    int triBase = slice * TRI_SLICE;

    // stage screen constants for the whole slice
    {
        const ulonglong2* src = &g_scr[((size_t)b * NF + triBase) * 2];
        for (int i = threadIdx.x; i < TRI_SLICE * 2; i += THREADS)
            s_scr[i] = src[i];
    }

    int p0 = ptile * PTS_BLOCK + threadIdx.x;      // second point = p0 + THREADS
    const float* P = points + ((size_t)b * NP + p0) * 3;
    u64 px = pk2(P[0], P[THREADS * 3 + 0]);
    u64 py = pk2(P[1], P[THREADS * 3 + 1]);
    u64 pz = pk2(P[2], P[THREADS * 3 + 2]);

    float best0 = CUDART_INF_F, best1 = CUDART_INF_F;
    u64 nbest2 = pk2(-CUDART_INF_F, -CUDART_INF_F);

    const u64 NEG2    = 0xC0000000C0000000ULL;     // (-2, -2)
    const u64 NEGONE2 = 0xBF800000BF800000ULL;     // (-1, -1)

    int idx0 = b * NP + p0;
    int idx1 = idx0 + THREADS;

    __syncthreads();

    const ulonglong2* triTab = &g_tri[((size_t)b * NF + triBase) * 9];

#pragma unroll 2
    for (int t = 0; t < TRI_SLICE; ++t) {
        // ---- screen: plane-distance lower bound ----
        ulonglong2 sa = s_scr[2 * t];
        ulonglong2 sb = s_scr[2 * t + 1];
        u64 z  = f2fma(pz, sb.x, f2fma(py, sa.y, f2fma(px, sa.x, sb.y)));
        u64 zz = f2mul(z, z);
        u64 ds = f2add(zz, nbest2);                // zz - best (per half)
        unsigned sg = (unsigned)ds | (unsigned)(ds >> 32);

        if (__any_sync(0xffffffffu, ((int)sg) < 0)) {
            // ---- full evaluation (rare) ----
            const ulonglong2* gt = triTab + (size_t)t * 9;
            ulonglong2 c0 = gt[0], c1 = gt[1], c2 = gt[2], c3 = gt[3], c4 = gt[4];
            ulonglong2 c5 = gt[5], c6 = gt[6], c7 = gt[7], c8 = gt[8];
            u64 nax = c0.x, nay = c0.y, naz = c1.x, abx = c1.y, aby = c2.x, abz = c2.y;
            u64 acx = c3.x, acy = c3.y, acz = c4.x, aa = c4.y, cc = c5.x, nad = c5.y;
            u64 amd = c6.x, bb = c6.y, raa = c7.x, rcc = c7.y, rbb = c8.x, den = c8.y;

            u64 apx = f2add(px, nax);
            u64 apy = f2add(py, nay);
            u64 apz = f2add(pz, naz);

            u64 d1 = f2fma(abz, apz, f2fma(aby, apy, f2mul(abx, apx)));
            u64 d2 = f2fma(acz, apz, f2fma(acy, apy, f2mul(acx, apx)));
            u64 pp = f2fma(apz, apz, f2fma(apy, apy, f2mul(apx, apx)));

            // edge AB (pp-relative, <= 0)
            u64 uA = f2clamp(d1, aa);
            u64 sA = f2fma(d1, NEG2, uA);
            u64 qA = f2mul(f2mul(uA, raa), sA);
            // edge AC
            u64 uC = f2clamp(d2, cc);
            u64 sC = f2fma(d2, NEG2, uC);
            u64 qC = f2mul(f2mul(uC, rcc), sC);
            // edge BC
            u64 e46 = f2fma(d1, NEGONE2, f2add(d2, amd));
            u64 uB  = f2clamp(e46, bb);
            u64 sB  = f2fma(e46, NEG2, uB);
            u64 qB  = f2mul(f2mul(uB, rbb), sB);
            u64 aa2 = f2fma(d1, NEG2, aa);
            u64 qBC = f2add(qB, aa2);

            // inside test (interior distance^2 == zz, already computed)
            u64 vbp = f2fma(nad, d2, f2mul(cc, d1));
            u64 vcp = f2fma(nad, d1, f2mul(aa, d2));
            u64 dvs = f2fma(f2add(vbp, vcp), NEGONE2, den);

            // half 0
            {
                unsigned badb = (unsigned)vbp | (unsigned)vcp | (unsigned)dvs;
                unsigned msk  = (unsigned)(((int)badb) >> 31) & 0x7fc00000u;
                float qg = __uint_as_float((unsigned)zz | msk);   // NaN if outside
                float me = fminf(fminf(lo2(qA), lo2(qC)), lo2(qBC));
                float m  = fminf(lo2(pp) + me, qg);
                best0 = fminf(best0, m);
            }
            // half 1
            {
                unsigned badb = (unsigned)(vbp >> 32) | (unsigned)(vcp >> 32) | (unsigned)(dvs >> 32);
                unsigned msk  = (unsigned)(((int)badb) >> 31) & 0x7fc00000u;
                float qg = __uint_as_float((unsigned)(zz >> 32) | msk);
                float me = fminf(fminf(hi2(qA), hi2(qC)), hi2(qBC));
                float m  = fminf(hi2(pp) + me, qg);
                best1 = fminf(best1, m);
            }
            nbest2 = pk2(-best0, -best1);
        }

        // ---- periodic cross-slice sharing ----
        if ((t & 255) == 255) {
            atomicMin((int*)&g_mind2[idx0], __float_as_int(fmaxf(best0, 0.0f)));
            atomicMin((int*)&g_mind2[idx1], __float_as_int(fmaxf(best1, 0.0f)));
            best0 = fminf(best0, g_mind2[idx0]);
            best1 = fminf(best1, g_mind2[idx1]);
            nbest2 = pk2(-best0, -best1);
        }
    }

    atomicMin((int*)&g_mind2[idx0], __float_as_int(fmaxf(best0, 0.0f)));
    atomicMin((int*)&g_mind2[idx1], __float_as_int(fmaxf(best1, 0.0f)));
}

// ---------------------------------------------------------------------------
// Kernel 4: finalize — both batches concurrently (two 512-thread halves)
// ---------------------------------------------------------------------------
__device__ __forceinline__ float warpSum(float v) {
#pragma unroll
    for (int o = 16; o > 0; o >>= 1) v += __shfl_down_sync(0xffffffffu, v, o);
    return v;
}
__device__ __forceinline__ float warpMax(float v) {
#pragma unroll
    for (int o = 16; o > 0; o >>= 1) v = fmaxf(v, __shfl_down_sync(0xffffffffu, v, o));
    return v;
}
__device__ __forceinline__ float warpMin(float v) {
#pragma unroll
    for (int o = 16; o > 0; o >>= 1) v = fminf(v, __shfl_down_sync(0xffffffffu, v, o));
    return v;
}

__global__ void finalize_kernel(const float* __restrict__ verts,
                                float* __restrict__ out) {
    __shared__ float s_sum[32], s_max[32], s_min[32];
    __shared__ float s_loss[2];
    int tid  = threadIdx.x;
    int b    = tid >> 9;
    int lt   = tid & 511;
    int wid  = tid >> 5;
    int lane = tid & 31;

    float sum = 0.0f;
    for (int i = lt; i < NP; i += 512) sum += g_mind2[b * NP + i];

    float ymax = -CUDART_INF_F, ymin = CUDART_INF_F;
    for (int i = lt; i < NV; i += 512) {
        float y = verts[((size_t)b * NV + i) * 3 + 1];
        ymax = fmaxf(ymax, y);
        ymin = fminf(ymin, y);
    }

    sum  = warpSum(sum);
    ymax = warpMax(ymax);
    ymin = warpMin(ymin);
    if (lane == 0) { s_sum[wid] = sum; s_max[wid] = ymax; s_min[wid] = ymin; }
    __syncthreads();

    if (lt < 32) {
        int base = b * 16;
        float v  = (lane < 16) ? s_sum[base + lane] : 0.0f;
        float mx = (lane < 16) ? s_max[base + lane] : -CUDART_INF_F;
        float mn = (lane < 16) ? s_min[base + lane] : CUDART_INF_F;
        v  = warpSum(v);
        mx = warpMax(mx);
        mn = warpMin(mn);
        if (lane == 0) s_loss[b] = sqrtf(v) / (mx - mn);
    }
    __syncthreads();

    if (tid == 0) out[0] = 0.5f * (s_loss[0] + s_loss[1]);
}

// ---------------------------------------------------------------------------
// Entry point
// ---------------------------------------------------------------------------
extern "C" void kernel_launch(void* const* d_in, const int* in_sizes, int n_in,
                              void* d_out, int out_size) {
    const float* points = (const float*)d_in[0];  // body_verts [2,8192,3]
    const float* verts  = (const float*)d_in[1];  // mesh_verts [2,4098,3]
    const int*   faces  = (const int*)d_in[2];    // faces      [2,8192,3]
    float* out = (float*)d_out;

    init_kernel<<<(NB * NP + 255) / 256, 256>>>();
    prep_kernel<<<(NB * NF + 255) / 256, 256>>>(verts, faces);
    main_kernel<<<MAIN_BLOCKS + CORR_BLOCKS, THREADS>>>(points, verts, faces);
    finalize_kernel<<<1, 1024>>>(verts, out);
}

// round 17
// speedup vs baseline: 1.0057x; 1.0057x over previous
#include <cuda_runtime.h>
#include <math_constants.h>

// Problem shapes (PointCloudMeshGridLoss_79070347920145)
#define NB 2
#define NP 8192
#define NV 4098
#define NF 8192
#define EPSF 1e-12f

#define THREADS     256
#define PTS_BLOCK   512               // 2 points per thread (packed f32x2)
#define PTILES      16                // NP / PTS_BLOCK
#define SLICES      8
#define TRI_SLICE   1024              // NF / SLICES
#define MAIN_BLOCKS (NB * PTILES * SLICES)   // 256
#define CORR_BLOCKS 64                // NB * (NP/256)
#define DEG_MAX     512

typedef unsigned long long u64;

// Screen consts per tri: (nx,ny),(nz,c3z) pre-duplicated = 2 ulonglong2 (32B)
__device__ ulonglong2 g_scr[NB * NF * 2];
// Full consts per tri: 18 u64 = 9 ulonglong2 (144B)
// j0:(nax,nay) j1:(naz,abx) j2:(aby,abz) j3:(acx,acy) j4:(acz,aa)
// j5:(cc,nad)  j6:(amd,bb)  j7:(raa,rcc) j8:(rbb,den)
__device__ ulonglong2 g_tri[NB * NF * 9];
__device__ float      g_mind2[NB * NP];
__device__ int        g_degcnt[NB];
__device__ int        g_deglist[NB][DEG_MAX];

// ---------------- packed f32x2 helpers ----------------
__device__ __forceinline__ u64 pk2(float lo, float hi) {
    return ((u64)__float_as_uint(hi) << 32) | (u64)__float_as_uint(lo);
}
__device__ __forceinline__ float lo2(u64 v) { return __uint_as_float((unsigned)v); }
__device__ __forceinline__ float hi2(u64 v) { return __uint_as_float((unsigned)(v >> 32)); }
__device__ __forceinline__ u64 f2fma(u64 a, u64 b, u64 c) {
    u64 d; asm("fma.rn.f32x2 %0, %1, %2, %3;" : "=l"(d) : "l"(a), "l"(b), "l"(c)); return d;
}
__device__ __forceinline__ u64 f2mul(u64 a, u64 b) {
    u64 d; asm("mul.rn.f32x2 %0, %1, %2;" : "=l"(d) : "l"(a), "l"(b)); return d;
}
__device__ __forceinline__ u64 f2add(u64 a, u64 b) {
    u64 d; asm("add.rn.f32x2 %0, %1, %2;" : "=l"(d) : "l"(a), "l"(b)); return d;
}
__device__ __forceinline__ u64 f2clamp(u64 v, u64 hi) {   // per-half clamp to [0, hi]
    float a = fminf(fmaxf(lo2(v), 0.0f), lo2(hi));
    float b = fminf(fmaxf(hi2(v), 0.0f), hi2(hi));
    return pk2(a, b);
}

// ---------------------------------------------------------------------------
// Kernel 1: init
// ---------------------------------------------------------------------------
__global__ void init_kernel() {
    int i = blockIdx.x * blockDim.x + threadIdx.x;
    if (i < NB * NP) g_mind2[i] = CUDART_INF_F;
    if (i < NB) g_degcnt[i] = 0;
}

// ---------------------------------------------------------------------------
// Kernel 2: per-triangle precompute
// ---------------------------------------------------------------------------
__global__ void prep_kernel(const float* __restrict__ verts,
                            const int*   __restrict__ faces) {
    int idx = blockIdx.x * blockDim.x + threadIdx.x;
    if (idx >= NB * NF) return;
    int b = idx / NF;

    const int* fc = faces + (size_t)idx * 3;
    const float* vb = verts + (size_t)b * NV * 3;
    int ia = fc[0], ib = fc[1], ic = fc[2];

    float ax = vb[ia * 3 + 0], ay = vb[ia * 3 + 1], az = vb[ia * 3 + 2];
    float bx = vb[ib * 3 + 0], by = vb[ib * 3 + 1], bz = vb[ib * 3 + 2];
    float cx = vb[ic * 3 + 0], cy = vb[ic * 3 + 1], cz = vb[ic * 3 + 2];

    float abx = bx - ax, aby = by - ay, abz = bz - az;
    float acx = cx - ax, acy = cy - ay, acz = cz - az;

    float aa = abx * abx + aby * aby + abz * abz;
    float ad = abx * acx + aby * acy + abz * acz;
    float cc = acx * acx + acy * acy + acz * acz;
    float bb = aa + cc - 2.0f * ad;                 // |bc|^2
    float den = aa * cc - ad * ad;                  // |ab x ac|^2

    bool deg = (aa < 1e-9f) || (cc < 1e-9f) || (bb < 1e-9f) || (den < 1e-6f);
    if (deg) {
        int w = atomicAdd(&g_degcnt[b], 1);
        if (w < DEG_MAX) g_deglist[b][w] = idx - b * NF;
    }

    float raa = 1.0f / fmaxf(aa, EPSF);
    float rcc = 1.0f / fmaxf(cc, EPSF);
    float rbb = 1.0f / fmaxf(bb, EPSF);

    // unit normal (screen lower bound); disabled for degenerate faces
    float nxv = aby * acz - abz * acy;
    float nyv = abz * acx - abx * acz;
    float nzv = abx * acy - aby * acx;
    float rn = rsqrtf(fmaxf(den, 1e-30f));
    nxv *= rn; nyv *= rn; nzv *= rn;
    float c3z = -(nxv * ax + nyv * ay + nzv * az);
    if (deg) { nxv = 0.0f; nyv = 0.0f; nzv = 0.0f; c3z = 1e30f; }

#define DUP(x) pk2((x), (x))
    ulonglong2* sc = &g_scr[(size_t)idx * 2];
    sc[0] = make_ulonglong2(DUP(nxv), DUP(nyv));
    sc[1] = make_ulonglong2(DUP(nzv), DUP(c3z));

    ulonglong2* o = &g_tri[(size_t)idx * 9];
    o[0] = make_ulonglong2(DUP(-ax), DUP(-ay));
    o[1] = make_ulonglong2(DUP(-az), DUP(abx));
    o[2] = make_ulonglong2(DUP(aby), DUP(abz));
    o[3] = make_ulonglong2(DUP(acx), DUP(acy));
    o[4] = make_ulonglong2(DUP(acz), DUP(aa));
    o[5] = make_ulonglong2(DUP(cc),  DUP(-ad));
    o[6] = make_ulonglong2(DUP(aa - ad), DUP(bb));
    o[7] = make_ulonglong2(DUP(raa), DUP(rcc));
    o[8] = make_ulonglong2(DUP(rbb), DUP(den));
#undef DUP
}

// ---------------------------------------------------------------------------
// Exact reference cascade for one (point, triangle) — used by correction.
// ---------------------------------------------------------------------------
__device__ float cascade_dist2(float ppx, float ppy, float ppz,
                               const float* vb, const int* fc) {
    int ia = fc[0], ibv = fc[1], ic = fc[2];
    float ax = vb[ia * 3 + 0], ay = vb[ia * 3 + 1], az = vb[ia * 3 + 2];
    float bx = vb[ibv * 3 + 0], by = vb[ibv * 3 + 1], bz = vb[ibv * 3 + 2];
    float cx = vb[ic * 3 + 0], cy = vb[ic * 3 + 1], cz = vb[ic * 3 + 2];

    float abx = bx - ax, aby = by - ay, abz = bz - az;
    float acx = cx - ax, acy = cy - ay, acz = cz - az;

    float aa = abx * abx + aby * aby + abz * abz;
    float ad = abx * acx + aby * acy + abz * acz;
    float cc = acx * acx + acy * acy + acz * acz;
    float bbq = aa + cc - 2.0f * ad;
    float den = aa * cc - ad * ad;

    float raa  = 1.0f / fmaxf(aa, EPSF);
    float rcc  = 1.0f / fmaxf(cc, EPSF);
    float rbb  = 1.0f / fmaxf(bbq, EPSF);
    float rden = 1.0f / fmaxf(den, EPSF);

    float apx = ppx - ax, apy = ppy - ay, apz = ppz - az;

    float d1 = fmaf(abx, apx, fmaf(aby, apy, abz * apz));
    float d2 = fmaf(acx, apx, fmaf(acy, apy, acz * apz));
    float d3 = d1 - aa;
    float d4 = d2 - ad;
    float d5 = d1 - ad;
    float d6 = d2 - cc;

    float va = d3 * d6 - d5 * d4;
    float vbv = d5 * d2 - d1 * d6;
    float vcv = d1 * d4 - d3 * d2;

    float s = vbv * rden;
    float w = vcv * rden;

    float e46 = d4 - d3;
    float e56 = d5 - d6;
    bool c6 = (va <= 0.0f) && (e46 >= 0.0f) && (e56 >= 0.0f);
    float wbc = e46 * rbb;
    s = c6 ? (1.0f - wbc) : s;
    w = c6 ? wbc : w;

    bool c5 = (vbv <= 0.0f) && (d2 >= 0.0f) && (d6 <= 0.0f);
    s = c5 ? 0.0f : s;
    w = c5 ? (d2 * rcc) : w;

    bool c4 = (vcv <= 0.0f) && (d1 >= 0.0f) && (d3 <= 0.0f);
    s = c4 ? (d1 * raa) : s;
    w = c4 ? 0.0f : w;

    bool c3 = (d6 >= 0.0f) && (d5 <= d6);
    s = c3 ? 0.0f : s;
    w = c3 ? 1.0f : w;

    bool c2 = (d3 >= 0.0f) && (d4 <= d3);
    s = c2 ? 1.0f : s;
    w = c2 ? 0.0f : w;

    bool c1 = (d1 <= 0.0f) && (d2 <= 0.0f);
    s = c1 ? 0.0f : s;
    w = c1 ? 0.0f : w;

    float rx = apx - fmaf(s, abx, w * acx);
    float ry = apy - fmaf(s, aby, w * acy);
    float rz = apz - fmaf(s, abz, w * acz);
    return fmaf(rx, rx, fmaf(ry, ry, rz * rz));
}

// ---------------------------------------------------------------------------
// Kernel 3: main — plane-distance screening + rare full evaluation.
// Blocks [0,64): correction for degenerate faces (exact reference cascade).
// Blocks [64,320): screened scan.
// ---------------------------------------------------------------------------
__global__ __launch_bounds__(THREADS, 2)
void main_kernel(const float* __restrict__ points,
                 const float* __restrict__ verts,
                 const int*   __restrict__ faces) {
    __shared__ ulonglong2 s_scr[TRI_SLICE * 2];   // 32 KB

    if (blockIdx.x < CORR_BLOCKS) {
        // ---- correction role ----
        int cbid = blockIdx.x;
        int b = cbid >> 5;                         // 32 blocks per batch
        int n = min(g_degcnt[b], DEG_MAX);
        if (n == 0) return;
        int p = (cbid & 31) * THREADS + threadIdx.x;
        const float* pp_ = points + ((size_t)b * NP + p) * 3;
        float ppx = pp_[0], ppy = pp_[1], ppz = pp_[2];
        const float* vb = verts + (size_t)b * NV * 3;
        float best = CUDART_INF_F;
        for (int df = 0; df < n; ++df) {
            int f = g_deglist[b][df];
            best = fminf(best, cascade_dist2(ppx, ppy, ppz, vb,
                                             faces + ((size_t)b * NF + f) * 3));
        }
        best = fmaxf(best, 0.0f);
        atomicMin((int*)&g_mind2[b * NP + p], __float_as_int(best));
        return;
    }

    // ---- main role ----
    int bid   = blockIdx.x - CORR_BLOCKS;          // 0..255
    int b     = bid >> 7;                          // 128 blocks per batch
    int rem   = bid & 127;
    int ptile = rem >> 3;
    int slice = rem & 7;
    int triBase = slice * TRI_SLICE;

    // stage screen constants for the whole slice
    {
        const ulonglong2* src = &g_scr[((size_t)b * NF + triBase) * 2];
        for (int i = threadIdx.x; i < TRI_SLICE * 2; i += THREADS)
            s_scr[i] = src[i];
    }

    int p0 = ptile * PTS_BLOCK + threadIdx.x;      // second point = p0 + THREADS
    const float* P = points + ((size_t)b * NP + p0) * 3;
    u64 px = pk2(P[0], P[THREADS * 3 + 0]);
    u64 py = pk2(P[1], P[THREADS * 3 + 1]);
    u64 pz = pk2(P[2], P[THREADS * 3 + 2]);

    float best0 = CUDART_INF_F, best1 = CUDART_INF_F;
    u64 nbest2 = pk2(-CUDART_INF_F, -CUDART_INF_F);

    const u64 NEG2    = 0xC0000000C0000000ULL;     // (-2, -2)
    const u64 NEGONE2 = 0xBF800000BF800000ULL;     // (-1, -1)

    int idx0 = b * NP + p0;
    int idx1 = idx0 + THREADS;

    __syncthreads();

    const ulonglong2* triTab = &g_tri[((size_t)b * NF + triBase) * 9];

#pragma unroll 2
    for (int t = 0; t < TRI_SLICE; ++t) {
        // ---- screen: plane-distance lower bound ----
        ulonglong2 sa = s_scr[2 * t];
        ulonglong2 sb = s_scr[2 * t + 1];
        u64 z  = f2fma(pz, sb.x, f2fma(py, sa.y, f2fma(px, sa.x, sb.y)));
        u64 zz = f2mul(z, z);
        u64 ds = f2add(zz, nbest2);                // zz - best (per half)
        unsigned sg = (unsigned)ds | (unsigned)(ds >> 32);

        if (__any_sync(0xffffffffu, ((int)sg) < 0)) {
            // ---- full evaluation (rare) ----
            const ulonglong2* gt = triTab + (size_t)t * 9;
            ulonglong2 c0 = gt[0], c1 = gt[1], c2 = gt[2], c3 = gt[3], c4 = gt[4];
            ulonglong2 c5 = gt[5], c6 = gt[6], c7 = gt[7], c8 = gt[8];
            u64 nax = c0.x, nay = c0.y, naz = c1.x, abx = c1.y, aby = c2.x, abz = c2.y;
            u64 acx = c3.x, acy = c3.y, acz = c4.x, aa = c4.y, cc = c5.x, nad = c5.y;
            u64 amd = c6.x, bb = c6.y, raa = c7.x, rcc = c7.y, rbb = c8.x, den = c8.y;

            u64 apx = f2add(px, nax);
            u64 apy = f2add(py, nay);
            u64 apz = f2add(pz, naz);

            u64 d1 = f2fma(abz, apz, f2fma(aby, apy, f2mul(abx, apx)));
            u64 d2 = f2fma(acz, apz, f2fma(acy, apy, f2mul(acx, apx)));
            u64 pp = f2fma(apz, apz, f2fma(apy, apy, f2mul(apx, apx)));

            // edge AB (pp-relative, <= 0)
            u64 uA = f2clamp(d1, aa);
            u64 sA = f2fma(d1, NEG2, uA);
            u64 qA = f2mul(f2mul(uA, raa), sA);
            // edge AC
            u64 uC = f2clamp(d2, cc);
            u64 sC = f2fma(d2, NEG2, uC);
            u64 qC = f2mul(f2mul(uC, rcc), sC);
            // edge BC
            u64 e46 = f2fma(d1, NEGONE2, f2add(d2, amd));
            u64 uB  = f2clamp(e46, bb);
            u64 sB  = f2fma(e46, NEG2, uB);
            u64 qB  = f2mul(f2mul(uB, rbb), sB);
            u64 aa2 = f2fma(d1, NEG2, aa);
            u64 qBC = f2add(qB, aa2);

            // inside test (interior distance^2 == zz, already computed)
            u64 vbp = f2fma(nad, d2, f2mul(cc, d1));
            u64 vcp = f2fma(nad, d1, f2mul(aa, d2));
            u64 dvs = f2fma(f2add(vbp, vcp), NEGONE2, den);

            // half 0
            {
                unsigned badb = (unsigned)vbp | (unsigned)vcp | (unsigned)dvs;
                unsigned msk  = (unsigned)(((int)badb) >> 31) & 0x7fc00000u;
                float qg = __uint_as_float((unsigned)zz | msk);   // NaN if outside
                float me = fminf(fminf(lo2(qA), lo2(qC)), lo2(qBC));
                float m  = fminf(lo2(pp) + me, qg);
                best0 = fminf(best0, m);
            }
            // half 1
            {
                unsigned badb = (unsigned)(vbp >> 32) | (unsigned)(vcp >> 32) | (unsigned)(dvs >> 32);
                unsigned msk  = (unsigned)(((int)badb) >> 31) & 0x7fc00000u;
                float qg = __uint_as_float((unsigned)(zz >> 32) | msk);
                float me = fminf(fminf(hi2(qA), hi2(qC)), hi2(qBC));
                float m  = fminf(hi2(pp) + me, qg);
                best1 = fminf(best1, m);
            }
            nbest2 = pk2(-best0, -best1);
        }

        // ---- periodic cross-slice sharing ----
        if ((t & 255) == 255) {
            atomicMin((int*)&g_mind2[idx0], __float_as_int(fmaxf(best0, 0.0f)));
            atomicMin((int*)&g_mind2[idx1], __float_as_int(fmaxf(best1, 0.0f)));
            best0 = fminf(best0, g_mind2[idx0]);
            best1 = fminf(best1, g_mind2[idx1]);
            nbest2 = pk2(-best0, -best1);
        }
    }

    atomicMin((int*)&g_mind2[idx0], __float_as_int(fmaxf(best0, 0.0f)));
    atomicMin((int*)&g_mind2[idx1], __float_as_int(fmaxf(best1, 0.0f)));
}

// ---------------------------------------------------------------------------
// Kernel 4: finalize — both batches concurrently (two 512-thread halves)
// ---------------------------------------------------------------------------
__device__ __forceinline__ float warpSum(float v) {
#pragma unroll
    for (int o = 16; o > 0; o >>= 1) v += __shfl_down_sync(0xffffffffu, v, o);
    return v;
}
__device__ __forceinline__ float warpMax(float v) {
#pragma unroll
    for (int o = 16; o > 0; o >>= 1) v = fmaxf(v, __shfl_down_sync(0xffffffffu, v, o));
    return v;
}
__device__ __forceinline__ float warpMin(float v) {
#pragma unroll
    for (int o = 16; o > 0; o >>= 1) v = fminf(v, __shfl_down_sync(0xffffffffu, v, o));
    return v;
}

__global__ void finalize_kernel(const float* __restrict__ verts,
                                float* __restrict__ out) {
    __shared__ float s_sum[32], s_max[32], s_min[32];
    __shared__ float s_loss[2];
    int tid  = threadIdx.x;
    int b    = tid >> 9;
    int lt   = tid & 511;
    int wid  = tid >> 5;
    int lane = tid & 31;

    float sum = 0.0f;
    for (int i = lt; i < NP; i += 512) sum += g_mind2[b * NP + i];

    float ymax = -CUDART_INF_F, ymin = CUDART_INF_F;
    for (int i = lt; i < NV; i += 512) {
        float y = verts[((size_t)b * NV + i) * 3 + 1];
        ymax = fmaxf(ymax, y);
        ymin = fminf(ymin, y);
    }

    sum  = warpSum(sum);
    ymax = warpMax(ymax);
    ymin = warpMin(ymin);
    if (lane == 0) { s_sum[wid] = sum; s_max[wid] = ymax; s_min[wid] = ymin; }
    __syncthreads();

    if (lt < 32) {
        int base = b * 16;
        float v  = (lane < 16) ? s_sum[base + lane] : 0.0f;
        float mx = (lane < 16) ? s_max[base + lane] : -CUDART_INF_F;
        float mn = (lane < 16) ? s_min[base + lane] : CUDART_INF_F;
        v  = warpSum(v);
        mx = warpMax(mx);
        mn = warpMin(mn);
        if (lane == 0) s_loss[b] = sqrtf(v) / (mx - mn);
    }
    __syncthreads();

    if (tid == 0) out[0] = 0.5f * (s_loss[0] + s_loss[1]);
}

// ---------------------------------------------------------------------------
// Entry point
// ---------------------------------------------------------------------------
extern "C" void kernel_launch(void* const* d_in, const int* in_sizes, int n_in,
                              void* d_out, int out_size) {
    const float* points = (const float*)d_in[0];  // body_verts [2,8192,3]
    const float* verts  = (const float*)d_in[1];  // mesh_verts [2,4098,3]
    const int*   faces  = (const int*)d_in[2];    // faces      [2,8192,3]
    float* out = (float*)d_out;

    init_kernel<<<(NB * NP + 255) / 256, 256>>>();
    prep_kernel<<<(NB * NF + 255) / 256, 256>>>(verts, faces);
    main_kernel<<<MAIN_BLOCKS + CORR_BLOCKS, THREADS>>>(points, verts, faces);
    finalize_kernel<<<1, 1024>>>(verts, out);
}